// round 12
// baseline (speedup 1.0000x reference)
#include <cuda_runtime.h>
#include <cuda_bf16.h>
#include <math_constants.h>

// ---------------------------------------------------------------------------
// GCNLayer_V2: trimmed-mean neighbor aggregation + linear + bias + relu
// FUSED single-kernel version: block = 32 nodes; phase A aggregates into a
// shared 32x128 tile, phase B multiplies it by W (+bias, relu) and stores.
// R12: __launch_bounds__(256,4) -> <=64 regs -> 4 resident blocks/SM.
//
// Inputs (metadata order):
//   d_in[0] h      float [20000,128]
//   d_in[1] norm   float [20000,1]
//   d_in[2] weight float [128,128]
//   d_in[3] bias   float [128]
//   d_in[4] nbr    int32 [20000,32]
//   d_in[5] deg    int32 [20000]
// Output: float [20000,128] = relu(accum @ W + b)
// ---------------------------------------------------------------------------

#define NNODE 20000
#define FDIM 128
#define DMAX 32
#define BN 32              // nodes per block (20000 = 625 * 32, no tail)

typedef unsigned long long ull;

// ---------------------------------------------------------------------------
// Compile-time trim bound. Matches runtime floorf(__fmul_rn(n,0.45f)).
// ---------------------------------------------------------------------------
__host__ __device__ constexpr int trim_b(int n) {
    int braw = n / 2 - (1 - (n & 1));
    int bcap = (int)((float)n * 0.45f);
    int b = braw < bcap ? braw : bcap;
    return b < 1 ? 1 : b;
}
__host__ __device__ constexpr int union_lo(int nmin, int nmax) {
    int m = 1 << 30;
    for (int n = nmin; n <= nmax; ++n) { int v = trim_b(n); if (v < m) m = v; }
    return m;
}
__host__ __device__ constexpr int union_hi(int nmin, int nmax) {
    int M = 0;
    for (int n = nmin; n <= nmax; ++n) { int v = n - trim_b(n); if (v > M) M = v; }
    return M;
}
__host__ __device__ constexpr int next_pow2c(int n) {
    int p = 1;
    while (p < n) p <<= 1;
    return p;
}

// ---------------------------------------------------------------------------
// Batcher odd-even merge sort network (pow2), generated at compile time.
// ---------------------------------------------------------------------------
template <int S>
struct OEMSNet {
    int a[200];
    int b[200];
    int count;

    __host__ __device__ constexpr void cmp(int i, int j) {
        a[count] = i; b[count] = j; ++count;
    }
    __host__ __device__ constexpr void merge(int lo, int n, int r) {
        int m = r * 2;
        if (m < n) {
            merge(lo, n, m);
            merge(lo + r, n, m);
            for (int i = lo + r; i + r < lo + n; i += m) cmp(i, i + r);
        } else {
            cmp(lo, lo + r);
        }
    }
    __host__ __device__ constexpr void sort(int lo, int n) {
        if (n > 1) {
            int m = n / 2;
            sort(lo, m);
            sort(lo + m, m);
            merge(lo, n, 1);
        }
    }
    __host__ __device__ constexpr OEMSNet() : a(), b(), count(0) { sort(0, S); }
};

// ---------------------------------------------------------------------------
// Class network over NW wires, pruned twice (sentinel + window liveness).
// ---------------------------------------------------------------------------
template <int NW, int ULO, int UHI>
struct ClassNet {
    int a[200];
    int b[200];
    int count;

    __host__ __device__ constexpr ClassNet() : a(), b(), count(0) {
        constexpr int P = next_pow2c(NW);
        OEMSNet<P> full{};

        int ta[200] = {};
        int tb[200] = {};
        int tc = 0;
        for (int p = 0; p < full.count; ++p)
            if (full.b[p] < NW) { ta[tc] = full.a[p]; tb[tc] = full.b[p]; ++tc; }

        bool live[64] = {};
        for (int i = ULO; i < UHI; ++i) live[i] = true;
        bool keep[200] = {};
        for (int p = tc - 1; p >= 0; --p) {
            if (live[ta[p]] || live[tb[p]]) {
                keep[p] = true;
                live[ta[p]] = true;
                live[tb[p]] = true;
            }
        }
        for (int p = 0; p < tc; ++p)
            if (keep[p]) { a[count] = ta[p]; b[count] = tb[p]; ++count; }
    }
};

// ---------------------------------------------------------------------------
// Per-feature trimmed aggregation for one node (identical numerics to the
// measured R9 version). Keys are order-preserving u32 munges with the slot
// index in the low 5 bits; CE = 2x IMNMX.U32; the window sum un-munges and
// fuses key*norm via FFMA.
// ---------------------------------------------------------------------------
template <int NW, int NMIN, int NMAX>
__device__ __forceinline__ float trimmed_cls(const float* __restrict__ h,
                                             const int* s_nbr,
                                             const float* s_norm,
                                             int n, int lo, int hi, int tid) {
    constexpr int ULO = union_lo(NMIN, NMAX);
    constexpr int UHI = union_hi(NMIN, NMAX);

    unsigned key[NW];
#pragma unroll
    for (int d = 0; d < NW; ++d) {
        if (d < n) {
            int src = s_nbr[d];
            unsigned u = __float_as_uint(__ldg(&h[src * FDIM + tid]));
            unsigned mask = (unsigned)((int)u >> 31) | 0x80000000u;
            unsigned m = u ^ mask;
            key[d] = (m & ~31u) | (unsigned)d;     // slot in low 5 bits
        } else {
            key[d] = 0xFFFFFFE0u | (unsigned)d;    // max sentinel
        }
    }

    constexpr ClassNet<NW, ULO, UHI> net{};
#pragma unroll
    for (int p = 0; p < net.count; ++p) {
        const int i = net.a[p];
        const int l = net.b[p];
        unsigned ki = key[i], kl = key[l];
        key[i] = umin(ki, kl);      // IMNMX.U32
        key[l] = umax(ki, kl);      // IMNMX.U32
    }

    float ts = 0.0f;
#pragma unroll
    for (int r = ULO; r < UHI; ++r) {
        unsigned m = key[r];
        int slot = (int)(m & 31u);
        unsigned mask = (~(unsigned)((int)m >> 31)) | 0x80000000u;
        float x = __uint_as_float(m ^ mask);
        bool sel = (r >= lo) && (r < hi);
        float kk = sel ? x : 0.0f;
        ts = fmaf(kk, s_norm[slot], ts);
    }
    return ts;
}

// ---------------------------------------------------------------------------
// f32x2 helpers for the gemm phase
// ---------------------------------------------------------------------------
__device__ __forceinline__ void fma2(ull& d, ull a, ull b) {
    asm("fma.rn.f32x2 %0, %1, %2, %0;" : "+l"(d) : "l"(a), "l"(b));
}
__device__ __forceinline__ ull dup2(float x) {
    ull r;
    asm("mov.b64 %0, {%1, %1};" : "=l"(r) : "f"(x));
    return r;
}
__device__ __forceinline__ void unpack2(float& lo, float& hi, ull v) {
    asm("mov.b64 {%0, %1}, %2;" : "=f"(lo), "=f"(hi) : "l"(v));
}

// ---------------------------------------------------------------------------
// Fused kernel: 256 threads, 32 nodes per block, grid = 625.
// Phase A: warps 0-3 aggregate even-pair node, warps 4-7 the odd one, over
//          16 iterations (branch dispatch stays warp-coherent). Results land
//          in the shared As[32][128] tile.
// Phase B: 32x128 GEMM tile: thread (tx,ty) owns 4 rows x 4 cols. W rows come
//          as coalesced LDG.128 (L1-resident across blocks); A comes as
//          warp-broadcast LDS.64; column-pair packed FFMA2 accumulators.
// 4 resident blocks/SM (regs capped at 64) give 32 warps to cover the sort
// network's dependency-chain stalls and stagger phases across blocks.
// ---------------------------------------------------------------------------
__global__ __launch_bounds__(256, 4)
void fused_kernel(const float* __restrict__ h,
                  const float* __restrict__ norm,
                  const float* __restrict__ W,
                  const float* __restrict__ bias,
                  const int* __restrict__ nbr,
                  const int* __restrict__ deg,
                  float* __restrict__ out) {
    __shared__ float As[BN][FDIM];        // 16 KB aggregated tile
    __shared__ int   sNbr[BN][DMAX];      // 4 KB
    __shared__ float sNrm[BN][DMAX];      // 4 KB
    __shared__ int   sDeg[BN];
    __shared__ float sNd[BN];

    int tid = threadIdx.x;
    int base = blockIdx.x * BN;

    // ---- header preload (coalesced; norm gather random but small) ----
#pragma unroll
    for (int k = 0; k < BN * DMAX / 256; ++k) {          // 4 iters
        int i = tid + k * 256;
        int src = __ldg(&nbr[base * DMAX + i]);
        sNbr[i >> 5][i & 31] = src;
        sNrm[i >> 5][i & 31] = __ldg(&norm[src]);
    }
    if (tid < BN) {
        sDeg[tid] = __ldg(&deg[base + tid]);
        sNd[tid] = __ldg(&norm[base + tid]);
    }
    __syncthreads();

    // ---- phase A: aggregation, 2 nodes per iteration, no inner syncs ----
    int half = tid >> 7;      // 0/1 -> which node of the pair (warp-aligned)
    int ftid = tid & 127;     // feature index
#pragma unroll 1
    for (int it = 0; it < BN / 2; ++it) {
        int nl = it * 2 + half;
        int node = base + nl;
        int n = sDeg[nl];
        float normd = sNd[nl];
        float self0 = __ldg(&h[node * FDIM + ftid]) * normd;
        const int* s_nbr = sNbr[nl];
        const float* s_norm = sNrm[nl];

        float acc;
        if (n <= 3) {
            acc = ((float)n * self0) * normd;
        } else {
            int braw = (n >> 1) - (1 - (n & 1));
            int bcap = (int)floorf(__fmul_rn((float)n, 0.45f));
            int b = min(braw, bcap);
            b = max(b, 1);
            int lo = b, hi = n - b;

            float ts;
            if (n <= 8)
                ts = trimmed_cls<8, 4, 8>(h, s_nbr, s_norm, n, lo, hi, ftid);
            else if (n <= 14)
                ts = trimmed_cls<14, 9, 14>(h, s_nbr, s_norm, n, lo, hi, ftid);
            else if (n <= 20)
                ts = trimmed_cls<20, 15, 20>(h, s_nbr, s_norm, n, lo, hi, ftid);
            else if (n <= 26)
                ts = trimmed_cls<26, 21, 26>(h, s_nbr, s_norm, n, lo, hi, ftid);
            else
                ts = trimmed_cls<32, 27, 32>(h, s_nbr, s_norm, n, lo, hi, ftid);

            acc = (ts + self0 * (float)(2 * b)) * normd;
        }
        As[nl][ftid] = acc;
    }
    __syncthreads();

    // ---- phase B: out[base..base+31] = relu(As @ W + bias) ----
    int tx = tid & 31;        // column group: cols tx*4 .. +3
    int ty = tid >> 5;        // row group:    rows ty*4 .. +3

    ull acc[8];               // acc[rr*2+c2]: (row ty*4+rr, cols tx*4+2c2..+1)
#pragma unroll
    for (int i = 0; i < 8; ++i) acc[i] = 0ull;

#pragma unroll 4
    for (int f2 = 0; f2 < FDIM / 2; ++f2) {
        // W rows 2*f2 and 2*f2+1, this thread's 4 columns (coalesced LDG.128)
        float4 w0 = __ldg(reinterpret_cast<const float4*>(W + (2 * f2) * FDIM) + tx);
        float4 w1 = __ldg(reinterpret_cast<const float4*>(W + (2 * f2 + 1) * FDIM) + tx);
        ull w0a = *reinterpret_cast<ull*>(&w0.x);
        ull w0b = *reinterpret_cast<ull*>(&w0.z);
        ull w1a = *reinterpret_cast<ull*>(&w1.x);
        ull w1b = *reinterpret_cast<ull*>(&w1.z);

#pragma unroll
        for (int rr = 0; rr < 4; ++rr) {
            float2 a = *reinterpret_cast<const float2*>(&As[ty * 4 + rr][2 * f2]);
            ull a0 = dup2(a.x);
            ull a1 = dup2(a.y);
            fma2(acc[rr * 2 + 0], a0, w0a);
            fma2(acc[rr * 2 + 1], a0, w0b);
            fma2(acc[rr * 2 + 0], a1, w1a);
            fma2(acc[rr * 2 + 1], a1, w1b);
        }
    }

    // epilogue: bias + relu + store (grid covers exactly 20000 rows)
    float4 bb = __ldg(reinterpret_cast<const float4*>(bias) + tx);
#pragma unroll
    for (int rr = 0; rr < 4; ++rr) {
        int row = base + ty * 4 + rr;
        float o0, o1, o2, o3;
        unpack2(o0, o1, acc[rr * 2 + 0]);
        unpack2(o2, o3, acc[rr * 2 + 1]);
        float4 v;
        v.x = fmaxf(o0 + bb.x, 0.0f);
        v.y = fmaxf(o1 + bb.y, 0.0f);
        v.z = fmaxf(o2 + bb.z, 0.0f);
        v.w = fmaxf(o3 + bb.w, 0.0f);
        *reinterpret_cast<float4*>(out + row * FDIM + tx * 4) = v;
    }
}

// ---------------------------------------------------------------------------
// launch
// ---------------------------------------------------------------------------

extern "C" void kernel_launch(void* const* d_in, const int* in_sizes, int n_in,
                              void* d_out, int out_size) {
    const float* h    = (const float*)d_in[0];
    const float* norm = (const float*)d_in[1];
    const float* W    = (const float*)d_in[2];
    const float* bias = (const float*)d_in[3];
    const int*   nbr  = (const int*)d_in[4];
    const int*   deg  = (const int*)d_in[5];
    float* out = (float*)d_out;

    int nnode = in_sizes[5];          // 20000
    int blocks = nnode / BN;          // 625 exactly

    fused_kernel<<<blocks, 256>>>(h, norm, W, bias, nbr, deg, out);
}

// round 13
// speedup vs baseline: 1.0179x; 1.0179x over previous
#include <cuda_runtime.h>
#include <cuda_bf16.h>
#include <math_constants.h>

// ---------------------------------------------------------------------------
// GCNLayer_V2: trimmed-mean neighbor aggregation + linear + bias + relu
// Split kernels. R13: dual-pipe sort — keys are non-negative finite float
// bit patterns so u32 and f32 comparisons agree; compare-exchanges are
// distributed across the alu (IMNMX) and fma (FMNMX) pipes to double the
// effective CE throughput per SMSP.
//
// Inputs (metadata order):
//   d_in[0] h      float [20000,128]
//   d_in[1] norm   float [20000,1]
//   d_in[2] weight float [128,128]
//   d_in[3] bias   float [128]
//   d_in[4] nbr    int32 [20000,32]
//   d_in[5] deg    int32 [20000]
// Output: float [20000,128] = relu(accum @ W + b)
// ---------------------------------------------------------------------------

#define NNODE 20000
#define NPAD 20032          // padded to a multiple of 64 (tail rows unused)
#define FDIM 128
#define DMAX 32

typedef unsigned long long ull;

// scratch for the aggregated features (device global: no allocation allowed)
__device__ float g_accum[NPAD * FDIM];

// ---------------------------------------------------------------------------
// Compile-time trim bound. Matches runtime floorf(__fmul_rn(n,0.45f)).
// ---------------------------------------------------------------------------
__host__ __device__ constexpr int trim_b(int n) {
    int braw = n / 2 - (1 - (n & 1));
    int bcap = (int)((float)n * 0.45f);
    int b = braw < bcap ? braw : bcap;
    return b < 1 ? 1 : b;
}
__host__ __device__ constexpr int union_lo(int nmin, int nmax) {
    int m = 1 << 30;
    for (int n = nmin; n <= nmax; ++n) { int v = trim_b(n); if (v < m) m = v; }
    return m;
}
__host__ __device__ constexpr int union_hi(int nmin, int nmax) {
    int M = 0;
    for (int n = nmin; n <= nmax; ++n) { int v = n - trim_b(n); if (v > M) M = v; }
    return M;
}
__host__ __device__ constexpr int next_pow2c(int n) {
    int p = 1;
    while (p < n) p <<= 1;
    return p;
}

// ---------------------------------------------------------------------------
// Batcher odd-even merge sort network (pow2), generated at compile time.
// ---------------------------------------------------------------------------
template <int S>
struct OEMSNet {
    int a[200];
    int b[200];
    int count;

    __host__ __device__ constexpr void cmp(int i, int j) {
        a[count] = i; b[count] = j; ++count;
    }
    __host__ __device__ constexpr void merge(int lo, int n, int r) {
        int m = r * 2;
        if (m < n) {
            merge(lo, n, m);
            merge(lo + r, n, m);
            for (int i = lo + r; i + r < lo + n; i += m) cmp(i, i + r);
        } else {
            cmp(lo, lo + r);
        }
    }
    __host__ __device__ constexpr void sort(int lo, int n) {
        if (n > 1) {
            int m = n / 2;
            sort(lo, m);
            sort(lo + m, m);
            merge(lo, n, 1);
        }
    }
    __host__ __device__ constexpr OEMSNet() : a(), b(), count(0) { sort(0, S); }
};

// ---------------------------------------------------------------------------
// Class network over NW wires, pruned twice (sentinel + window liveness).
// ---------------------------------------------------------------------------
template <int NW, int ULO, int UHI>
struct ClassNet {
    int a[200];
    int b[200];
    int count;

    __host__ __device__ constexpr ClassNet() : a(), b(), count(0) {
        constexpr int P = next_pow2c(NW);
        OEMSNet<P> full{};

        int ta[200] = {};
        int tb[200] = {};
        int tc = 0;
        for (int p = 0; p < full.count; ++p)
            if (full.b[p] < NW) { ta[tc] = full.a[p]; tb[tc] = full.b[p]; ++tc; }

        bool live[64] = {};
        for (int i = ULO; i < UHI; ++i) live[i] = true;
        bool keep[200] = {};
        for (int p = tc - 1; p >= 0; --p) {
            if (live[ta[p]] || live[tb[p]]) {
                keep[p] = true;
                live[ta[p]] = true;
                live[tb[p]] = true;
            }
        }
        for (int p = 0; p < tc; ++p)
            if (keep[p]) { a[count] = ta[p]; b[count] = tb[p]; ++count; }
    }
};

// ---------------------------------------------------------------------------
// Kernel 1: per-node, per-feature trimmed aggregation.
// Block = 128 threads (one per feature), grid = N nodes; 5 window-pruned
// class networks (I$-safe).
//
// Dual-pipe keys: munge = order-preserving u32 map, then >>1 and slot in the
// low 5 bits. All keys land in [0, 0x7F7FFFFF] = non-negative finite floats,
// where u32 ordering == f32 ordering. Compare-exchanges alternate between
// IMNMX.U32 (alu pipe) and FMNMX (fma pipe), 1/3 : 2/3, so the two 0.5/cyc
// SMSP pipes share the sort instead of serializing on alu. Sentinels
// 0x7F000000|slot are huge finite floats (no NaN/FTZ hazards for N(0,1) h).
// 6-bit mantissa truncation perturbs each term <= 2^-17 relative.
// ---------------------------------------------------------------------------

template <int NW, int NMIN, int NMAX>
__device__ __forceinline__ float trimmed_cls(const float* __restrict__ h,
                                             const int* s_nbr,
                                             const float* s_norm,
                                             int n, int lo, int hi, int tid) {
    constexpr int ULO = union_lo(NMIN, NMAX);
    constexpr int UHI = union_hi(NMIN, NMAX);

    unsigned key[NW];
#pragma unroll
    for (int d = 0; d < NW; ++d) {
        if (d < n) {
            int src = s_nbr[d];
            unsigned u = __float_as_uint(__ldg(&h[src * FDIM + tid]));
            // order-preserving munge: pos -> u|0x80000000, neg -> ~u
            unsigned mask = (unsigned)((int)u >> 31) | 0x80000000u;
            unsigned m = u ^ mask;
            // >>1 puts the key in non-negative-finite-float space
            key[d] = ((m >> 1) & ~31u) | (unsigned)d;   // slot in low 5 bits
        } else {
            key[d] = 0x7F000000u | (unsigned)d;         // huge finite sentinel
        }
    }

    constexpr ClassNet<NW, ULO, UHI> net{};
#pragma unroll
    for (int p = 0; p < net.count; ++p) {
        const int i = net.a[p];
        const int l = net.b[p];
        unsigned ki = key[i], kl = key[l];
        if (p % 3 == 0) {
            key[i] = umin(ki, kl);        // IMNMX.U32 (alu pipe)
            key[l] = umax(ki, kl);
        } else {
            float fi = __uint_as_float(ki);
            float fl = __uint_as_float(kl);
            key[i] = __float_as_uint(fminf(fi, fl));   // FMNMX (fma pipe)
            key[l] = __float_as_uint(fmaxf(fi, fl));
        }
    }

    // masked fused sum over the union window
    float ts = 0.0f;
#pragma unroll
    for (int r = ULO; r < UHI; ++r) {
        unsigned k = key[r];
        int slot = (int)(k & 31u);
        unsigned m2 = (k & ~31u) << 1;    // restore munged value (6 bits lost)
        unsigned mask = (~(unsigned)((int)m2 >> 31)) | 0x80000000u;
        float x = __uint_as_float(m2 ^ mask);
        bool sel = (r >= lo) && (r < hi);
        float kk = sel ? x : 0.0f;
        ts = fmaf(kk, s_norm[slot], ts);
    }
    return ts;
}

__global__ __launch_bounds__(FDIM)
void agg_kernel(const float* __restrict__ h,
                const float* __restrict__ norm,
                const int* __restrict__ nbr,
                const int* __restrict__ deg,
                int nnode) {
    int node = blockIdx.x;
    if (node >= nnode) return;
    int tid = threadIdx.x;

    __shared__ int s_nbr[DMAX];
    __shared__ float s_norm[DMAX];
    __shared__ int s_n;
    __shared__ float s_nd;

    if (tid < DMAX) {
        int src = nbr[node * DMAX + tid];
        s_nbr[tid] = src;
        s_norm[tid] = norm[src];
    }
    if (tid == 0) {
        s_n = deg[node];
        s_nd = norm[node];
    }
    __syncthreads();

    int n = s_n;                 // block-uniform
    float normd = s_nd;
    float self0 = h[node * FDIM + tid] * normd;

    float acc;
    if (n <= 3) {
        acc = ((float)n * self0) * normd;
    } else {
        int braw = (n >> 1) - (1 - (n & 1));
        int bcap = (int)floorf(__fmul_rn((float)n, 0.45f));
        int b = min(braw, bcap);
        b = max(b, 1);
        int lo = b, hi = n - b;

        float ts;
        if (n <= 8)
            ts = trimmed_cls<8, 4, 8>(h, s_nbr, s_norm, n, lo, hi, tid);
        else if (n <= 14)
            ts = trimmed_cls<14, 9, 14>(h, s_nbr, s_norm, n, lo, hi, tid);
        else if (n <= 20)
            ts = trimmed_cls<20, 15, 20>(h, s_nbr, s_norm, n, lo, hi, tid);
        else if (n <= 26)
            ts = trimmed_cls<26, 21, 26>(h, s_nbr, s_norm, n, lo, hi, tid);
        else
            ts = trimmed_cls<32, 27, 32>(h, s_nbr, s_norm, n, lo, hi, tid);

        acc = (ts + self0 * (float)(2 * b)) * normd;
    }
    g_accum[node * FDIM + tid] = acc;
}

// ---------------------------------------------------------------------------
// Kernel 2: out = relu(accum @ W + bias)   [R10 — measured 23.9us, unchanged]
// Tile = 64 rows x 64 cols, 128 threads, 8x4 register tile per thread.
// Grid = 313 row-tiles x 2 col-halves = 626 blocks; W half in 32KB smem.
// g_accum padded to 20032 rows -> single base pointer, immediate offsets.
// f32x2-packed accumulators over column pairs + fma.rn.f32x2.
// ---------------------------------------------------------------------------

#define GT_ROWS 64
#define GT_COLS 64
#define GEMM_SMEM_BYTES (FDIM * GT_COLS * 4)   // 32 KB

__device__ __forceinline__ void fma2(ull& d, ull a, ull b) {
    asm("fma.rn.f32x2 %0, %1, %2, %0;" : "+l"(d) : "l"(a), "l"(b));
}
__device__ __forceinline__ ull dup2(float x) {
    ull r;
    asm("mov.b64 %0, {%1, %1};" : "=l"(r) : "f"(x));
    return r;
}
__device__ __forceinline__ void unpack2(float& lo, float& hi, ull v) {
    asm("mov.b64 {%0, %1}, %2;" : "=f"(lo), "=f"(hi) : "l"(v));
}

__global__ __launch_bounds__(128, 5)
void gemm_kernel(const float* __restrict__ W,
                 const float* __restrict__ bias,
                 float* __restrict__ out,
                 int nnode) {
    extern __shared__ float Ws[];      // [128][64] : W rows, this block's col half

    int tid = threadIdx.x;
    int row0 = (blockIdx.x >> 1) * GT_ROWS;
    int col0 = (blockIdx.x & 1) * GT_COLS;

    // stage this column half of W (coalesced float4: 16 float4 per W row)
    {
#pragma unroll
        for (int i = 0; i < FDIM * GT_COLS / 4 / 128; ++i) {
            int idx = tid + i * 128;
            int f = idx >> 4;          // W row
            int c4 = idx & 15;         // float4 within the half-row
            *reinterpret_cast<float4*>(Ws + f * GT_COLS + c4 * 4) =
                *reinterpret_cast<const float4*>(W + f * FDIM + col0 + c4 * 4);
        }
    }
    __syncthreads();

    int tx = tid & 15;       // column group: cols col0 + tx*4 .. +3
    int ty = tid >> 4;       // row group:    rows row0 + ty*8 .. +7

    ull acc[16];             // acc[r*2+c2] = (row ty*8+r, cols tx*4+2c2..+1)
#pragma unroll
    for (int i = 0; i < 16; ++i) acc[i] = 0ull;

    const float* abase = g_accum + (row0 + ty * 8) * FDIM;   // padded: no clamp
    const ull* wbase = reinterpret_cast<const ull*>(Ws + tx * 4);

#pragma unroll 4
    for (int f2 = 0; f2 < FDIM / 2; ++f2) {
        // A: two f-values per row as one 8B broadcast load (immediate offsets)
        float2 av[8];
#pragma unroll
        for (int r = 0; r < 8; ++r)
            av[r] = __ldg(reinterpret_cast<const float2*>(abase + r * FDIM) + f2);

        // W: column pairs for f and f+1
        ull w0[2], w1[2];
        const ull* wp0 = wbase + (2 * f2) * (GT_COLS / 2);
        const ull* wp1 = wp0 + (GT_COLS / 2);
        w0[0] = wp0[0]; w0[1] = wp0[1];
        w1[0] = wp1[0]; w1[1] = wp1[1];

#pragma unroll
        for (int r = 0; r < 8; ++r) {
            ull a0 = dup2(av[r].x);
            ull a1 = dup2(av[r].y);
#pragma unroll
            for (int c2 = 0; c2 < 2; ++c2) {
                fma2(acc[r * 2 + c2], a0, w0[c2]);
                fma2(acc[r * 2 + c2], a1, w1[c2]);
            }
        }
    }

    // epilogue: bias + relu + store
    float bcol[4];
#pragma unroll
    for (int c = 0; c < 4; ++c) bcol[c] = __ldg(&bias[col0 + tx * 4 + c]);

#pragma unroll
    for (int r = 0; r < 8; ++r) {
        int row = row0 + ty * 8 + r;
        if (row < nnode) {
            float* orow = out + row * FDIM + col0 + tx * 4;
#pragma unroll
            for (int c2 = 0; c2 < 2; ++c2) {
                float lo, hi;
                unpack2(lo, hi, acc[r * 2 + c2]);
                float2 o;
                o.x = fmaxf(lo + bcol[2 * c2], 0.0f);
                o.y = fmaxf(hi + bcol[2 * c2 + 1], 0.0f);
                *reinterpret_cast<float2*>(orow + 2 * c2) = o;
            }
        }
    }
}

// ---------------------------------------------------------------------------
// launch
// ---------------------------------------------------------------------------

extern "C" void kernel_launch(void* const* d_in, const int* in_sizes, int n_in,
                              void* d_out, int out_size) {
    const float* h    = (const float*)d_in[0];
    const float* norm = (const float*)d_in[1];
    const float* W    = (const float*)d_in[2];
    const float* bias = (const float*)d_in[3];
    const int*   nbr  = (const int*)d_in[4];
    const int*   deg  = (const int*)d_in[5];
    float* out = (float*)d_out;

    int nnode = in_sizes[5];   // 20000

    cudaFuncSetAttribute(gemm_kernel,
                         cudaFuncAttributeMaxDynamicSharedMemorySize,
                         GEMM_SMEM_BYTES);

    agg_kernel<<<nnode, FDIM>>>(h, norm, nbr, deg, nnode);

    int row_tiles = (NPAD / GT_ROWS);                 // 313
    gemm_kernel<<<row_tiles * 2, 128, GEMM_SMEM_BYTES>>>(W, bias, out, nnode);
}

// round 14
// speedup vs baseline: 1.1550x; 1.1347x over previous
#include <cuda_runtime.h>
#include <cuda_bf16.h>
#include <math_constants.h>

// ---------------------------------------------------------------------------
// GCNLayer_V2: trimmed-mean neighbor aggregation + linear + bias + relu
// Split kernels. R14: munge-free float sort — keys are the raw h floats with
// the slot index embedded in the low 5 mantissa bits; FMNMX orders signed
// floats natively, so the gather needs 1 LOP3 and the window loop reads the
// key directly. Same CE count, ~20% fewer alu ops overall.
//
// Inputs (metadata order):
//   d_in[0] h      float [20000,128]
//   d_in[1] norm   float [20000,1]
//   d_in[2] weight float [128,128]
//   d_in[3] bias   float [128]
//   d_in[4] nbr    int32 [20000,32]
//   d_in[5] deg    int32 [20000]
// Output: float [20000,128] = relu(accum @ W + b)
// ---------------------------------------------------------------------------

#define NNODE 20000
#define NPAD 20032          // padded to a multiple of 64 (tail rows unused)
#define FDIM 128
#define DMAX 32

typedef unsigned long long ull;

// scratch for the aggregated features (device global: no allocation allowed)
__device__ float g_accum[NPAD * FDIM];

// ---------------------------------------------------------------------------
// Compile-time trim bound. Matches runtime floorf(__fmul_rn(n,0.45f)).
// ---------------------------------------------------------------------------
__host__ __device__ constexpr int trim_b(int n) {
    int braw = n / 2 - (1 - (n & 1));
    int bcap = (int)((float)n * 0.45f);
    int b = braw < bcap ? braw : bcap;
    return b < 1 ? 1 : b;
}
__host__ __device__ constexpr int union_lo(int nmin, int nmax) {
    int m = 1 << 30;
    for (int n = nmin; n <= nmax; ++n) { int v = trim_b(n); if (v < m) m = v; }
    return m;
}
__host__ __device__ constexpr int union_hi(int nmin, int nmax) {
    int M = 0;
    for (int n = nmin; n <= nmax; ++n) { int v = n - trim_b(n); if (v > M) M = v; }
    return M;
}
__host__ __device__ constexpr int next_pow2c(int n) {
    int p = 1;
    while (p < n) p <<= 1;
    return p;
}

// ---------------------------------------------------------------------------
// Batcher odd-even merge sort network (pow2), generated at compile time.
// ---------------------------------------------------------------------------
template <int S>
struct OEMSNet {
    int a[200];
    int b[200];
    int count;

    __host__ __device__ constexpr void cmp(int i, int j) {
        a[count] = i; b[count] = j; ++count;
    }
    __host__ __device__ constexpr void merge(int lo, int n, int r) {
        int m = r * 2;
        if (m < n) {
            merge(lo, n, m);
            merge(lo + r, n, m);
            for (int i = lo + r; i + r < lo + n; i += m) cmp(i, i + r);
        } else {
            cmp(lo, lo + r);
        }
    }
    __host__ __device__ constexpr void sort(int lo, int n) {
        if (n > 1) {
            int m = n / 2;
            sort(lo, m);
            sort(lo + m, m);
            merge(lo, n, 1);
        }
    }
    __host__ __device__ constexpr OEMSNet() : a(), b(), count(0) { sort(0, S); }
};

// ---------------------------------------------------------------------------
// Class network over NW wires, pruned twice (sentinel + window liveness).
// ---------------------------------------------------------------------------
template <int NW, int ULO, int UHI>
struct ClassNet {
    int a[200];
    int b[200];
    int count;

    __host__ __device__ constexpr ClassNet() : a(), b(), count(0) {
        constexpr int P = next_pow2c(NW);
        OEMSNet<P> full{};

        int ta[200] = {};
        int tb[200] = {};
        int tc = 0;
        for (int p = 0; p < full.count; ++p)
            if (full.b[p] < NW) { ta[tc] = full.a[p]; tb[tc] = full.b[p]; ++tc; }

        bool live[64] = {};
        for (int i = ULO; i < UHI; ++i) live[i] = true;
        bool keep[200] = {};
        for (int p = tc - 1; p >= 0; --p) {
            if (live[ta[p]] || live[tb[p]]) {
                keep[p] = true;
                live[ta[p]] = true;
                live[tb[p]] = true;
            }
        }
        for (int p = 0; p < tc; ++p)
            if (keep[p]) { a[count] = ta[p]; b[count] = tb[p]; ++count; }
    }
};

// ---------------------------------------------------------------------------
// Kernel 1: per-node, per-feature trimmed aggregation.
// Block = 128 threads (one per feature), grid = N nodes; 5 window-pruned
// class networks (I$-safe; 29 variants thrashed I$).
//
// Munge-free keys: key = h value with low 5 mantissa bits replaced by the
// slot index. FMNMX orders signed floats natively, so no order-preserving
// integer transform is needed. One CE = FMNMX pair (alu pipe, 2 ops; the
// proven minimum here — sm_103a has no fma-pipe min/max). The window loop
// uses the key itself as the value (<=2^-18 relative perturbation) and
// recovers slot = bits & 31 for the norm lookup. Sentinel = 0x7F000000|slot
// (~1.7e38, finite, sorts above all N(0,1) data; no NaN/inf hazards).
// ---------------------------------------------------------------------------

template <int NW, int NMIN, int NMAX>
__device__ __forceinline__ float trimmed_cls(const float* __restrict__ h,
                                             const int* s_nbr,
                                             const float* s_norm,
                                             int n, int lo, int hi, int tid) {
    constexpr int ULO = union_lo(NMIN, NMAX);
    constexpr int UHI = union_hi(NMIN, NMAX);

    float key[NW];
#pragma unroll
    for (int d = 0; d < NW; ++d) {
        if (d < n) {
            int src = s_nbr[d];
            unsigned u = __float_as_uint(__ldg(&h[src * FDIM + tid]));
            key[d] = __uint_as_float((u & ~31u) | (unsigned)d);  // 1 LOP3
        } else {
            key[d] = __uint_as_float(0x7F000000u | (unsigned)d); // huge finite
        }
    }

    constexpr ClassNet<NW, ULO, UHI> net{};
#pragma unroll
    for (int p = 0; p < net.count; ++p) {
        const int i = net.a[p];
        const int l = net.b[p];
        float ki = key[i], kl = key[l];
        key[i] = fminf(ki, kl);      // FMNMX
        key[l] = fmaxf(ki, kl);      // FMNMX
    }

    // masked fused sum over the union window: the key IS the value
    float ts = 0.0f;
#pragma unroll
    for (int r = ULO; r < UHI; ++r) {
        float x = key[r];
        int slot = (int)(__float_as_uint(x) & 31u);
        bool sel = (r >= lo) && (r < hi);
        float kk = sel ? x : 0.0f;
        ts = fmaf(kk, s_norm[slot], ts);
    }
    return ts;
}

__global__ __launch_bounds__(FDIM)
void agg_kernel(const float* __restrict__ h,
                const float* __restrict__ norm,
                const int* __restrict__ nbr,
                const int* __restrict__ deg,
                int nnode) {
    int node = blockIdx.x;
    if (node >= nnode) return;
    int tid = threadIdx.x;

    __shared__ int s_nbr[DMAX];
    __shared__ float s_norm[DMAX];
    __shared__ int s_n;
    __shared__ float s_nd;

    if (tid < DMAX) {
        int src = nbr[node * DMAX + tid];
        s_nbr[tid] = src;
        s_norm[tid] = norm[src];
    }
    if (tid == 0) {
        s_n = deg[node];
        s_nd = norm[node];
    }
    __syncthreads();

    int n = s_n;                 // block-uniform
    float normd = s_nd;
    float self0 = h[node * FDIM + tid] * normd;

    float acc;
    if (n <= 3) {
        acc = ((float)n * self0) * normd;
    } else {
        int braw = (n >> 1) - (1 - (n & 1));
        int bcap = (int)floorf(__fmul_rn((float)n, 0.45f));
        int b = min(braw, bcap);
        b = max(b, 1);
        int lo = b, hi = n - b;

        float ts;
        if (n <= 8)
            ts = trimmed_cls<8, 4, 8>(h, s_nbr, s_norm, n, lo, hi, tid);
        else if (n <= 14)
            ts = trimmed_cls<14, 9, 14>(h, s_nbr, s_norm, n, lo, hi, tid);
        else if (n <= 20)
            ts = trimmed_cls<20, 15, 20>(h, s_nbr, s_norm, n, lo, hi, tid);
        else if (n <= 26)
            ts = trimmed_cls<26, 21, 26>(h, s_nbr, s_norm, n, lo, hi, tid);
        else
            ts = trimmed_cls<32, 27, 32>(h, s_nbr, s_norm, n, lo, hi, tid);

        acc = (ts + self0 * (float)(2 * b)) * normd;
    }
    g_accum[node * FDIM + tid] = acc;
}

// ---------------------------------------------------------------------------
// Kernel 2: out = relu(accum @ W + bias)   [R10 — measured 23.9us, unchanged]
// Tile = 64 rows x 64 cols, 128 threads, 8x4 register tile per thread.
// Grid = 313 row-tiles x 2 col-halves = 626 blocks; W half in 32KB smem.
// g_accum padded to 20032 rows -> single base pointer, immediate offsets.
// f32x2-packed accumulators over column pairs + fma.rn.f32x2.
// ---------------------------------------------------------------------------

#define GT_ROWS 64
#define GT_COLS 64
#define GEMM_SMEM_BYTES (FDIM * GT_COLS * 4)   // 32 KB

__device__ __forceinline__ void fma2(ull& d, ull a, ull b) {
    asm("fma.rn.f32x2 %0, %1, %2, %0;" : "+l"(d) : "l"(a), "l"(b));
}
__device__ __forceinline__ ull dup2(float x) {
    ull r;
    asm("mov.b64 %0, {%1, %1};" : "=l"(r) : "f"(x));
    return r;
}
__device__ __forceinline__ void unpack2(float& lo, float& hi, ull v) {
    asm("mov.b64 {%0, %1}, %2;" : "=f"(lo), "=f"(hi) : "l"(v));
}

__global__ __launch_bounds__(128, 5)
void gemm_kernel(const float* __restrict__ W,
                 const float* __restrict__ bias,
                 float* __restrict__ out,
                 int nnode) {
    extern __shared__ float Ws[];      // [128][64] : W rows, this block's col half

    int tid = threadIdx.x;
    int row0 = (blockIdx.x >> 1) * GT_ROWS;
    int col0 = (blockIdx.x & 1) * GT_COLS;

    // stage this column half of W (coalesced float4: 16 float4 per W row)
    {
#pragma unroll
        for (int i = 0; i < FDIM * GT_COLS / 4 / 128; ++i) {
            int idx = tid + i * 128;
            int f = idx >> 4;          // W row
            int c4 = idx & 15;         // float4 within the half-row
            *reinterpret_cast<float4*>(Ws + f * GT_COLS + c4 * 4) =
                *reinterpret_cast<const float4*>(W + f * FDIM + col0 + c4 * 4);
        }
    }
    __syncthreads();

    int tx = tid & 15;       // column group: cols col0 + tx*4 .. +3
    int ty = tid >> 4;       // row group:    rows row0 + ty*8 .. +7

    ull acc[16];             // acc[r*2+c2] = (row ty*8+r, cols tx*4+2c2..+1)
#pragma unroll
    for (int i = 0; i < 16; ++i) acc[i] = 0ull;

    const float* abase = g_accum + (row0 + ty * 8) * FDIM;   // padded: no clamp
    const ull* wbase = reinterpret_cast<const ull*>(Ws + tx * 4);

#pragma unroll 4
    for (int f2 = 0; f2 < FDIM / 2; ++f2) {
        // A: two f-values per row as one 8B broadcast load (immediate offsets)
        float2 av[8];
#pragma unroll
        for (int r = 0; r < 8; ++r)
            av[r] = __ldg(reinterpret_cast<const float2*>(abase + r * FDIM) + f2);

        // W: column pairs for f and f+1
        ull w0[2], w1[2];
        const ull* wp0 = wbase + (2 * f2) * (GT_COLS / 2);
        const ull* wp1 = wp0 + (GT_COLS / 2);
        w0[0] = wp0[0]; w0[1] = wp0[1];
        w1[0] = wp1[0]; w1[1] = wp1[1];

#pragma unroll
        for (int r = 0; r < 8; ++r) {
            ull a0 = dup2(av[r].x);
            ull a1 = dup2(av[r].y);
#pragma unroll
            for (int c2 = 0; c2 < 2; ++c2) {
                fma2(acc[r * 2 + c2], a0, w0[c2]);
                fma2(acc[r * 2 + c2], a1, w1[c2]);
            }
        }
    }

    // epilogue: bias + relu + store
    float bcol[4];
#pragma unroll
    for (int c = 0; c < 4; ++c) bcol[c] = __ldg(&bias[col0 + tx * 4 + c]);

#pragma unroll
    for (int r = 0; r < 8; ++r) {
        int row = row0 + ty * 8 + r;
        if (row < nnode) {
            float* orow = out + row * FDIM + col0 + tx * 4;
#pragma unroll
            for (int c2 = 0; c2 < 2; ++c2) {
                float lo, hi;
                unpack2(lo, hi, acc[r * 2 + c2]);
                float2 o;
                o.x = fmaxf(lo + bcol[2 * c2], 0.0f);
                o.y = fmaxf(hi + bcol[2 * c2 + 1], 0.0f);
                *reinterpret_cast<float2*>(orow + 2 * c2) = o;
            }
        }
    }
}

// ---------------------------------------------------------------------------
// launch
// ---------------------------------------------------------------------------

extern "C" void kernel_launch(void* const* d_in, const int* in_sizes, int n_in,
                              void* d_out, int out_size) {
    const float* h    = (const float*)d_in[0];
    const float* norm = (const float*)d_in[1];
    const float* W    = (const float*)d_in[2];
    const float* bias = (const float*)d_in[3];
    const int*   nbr  = (const int*)d_in[4];
    const int*   deg  = (const int*)d_in[5];
    float* out = (float*)d_out;

    int nnode = in_sizes[5];   // 20000

    cudaFuncSetAttribute(gemm_kernel,
                         cudaFuncAttributeMaxDynamicSharedMemorySize,
                         GEMM_SMEM_BYTES);

    agg_kernel<<<nnode, FDIM>>>(h, norm, nbr, deg, nnode);

    int row_tiles = (NPAD / GT_ROWS);                 // 313
    gemm_kernel<<<row_tiles * 2, 128, GEMM_SMEM_BYTES>>>(W, bias, out, nnode);
}